// round 3
// baseline (speedup 1.0000x reference)
#include <cuda_runtime.h>
#include <cstdint>

// Problem constants (validated against in_sizes/out_size at launch).
#define DIM 64
#define MAX_SEG 100000

// Scratch: per-segment counts (400 KB). __device__ global per allocation rules.
__device__ float g_counts[MAX_SEG];

// ---------------------------------------------------------------------------
// Kernel 1: zero the output sums and the count array.
// ---------------------------------------------------------------------------
__global__ void zero_kernel(float4* __restrict__ out4, int n_out4, int num_seg) {
    int i = blockIdx.x * blockDim.x + threadIdx.x;
    int stride = gridDim.x * blockDim.x;
    for (int j = i; j < n_out4; j += stride)
        out4[j] = make_float4(0.f, 0.f, 0.f, 0.f);
    for (int j = i; j < num_seg; j += stride)
        g_counts[j] = 0.f;
}

// ---------------------------------------------------------------------------
// Kernel 2: scatter-add. 16 threads per row; each thread owns one float4
// (16 B) of the 256 B row. x read is fully coalesced. The accumulation uses
// red.global.add.v4.f32 (REDG, no return), which lands in L2 since the
// 25.6 MB output fits in the 126 MB L2.
// NOTE: index is int32 — JAX without x64 silently downcasts jnp.int64.
// ---------------------------------------------------------------------------
__global__ void __launch_bounds__(256) scatter_kernel(
    const float4* __restrict__ x4,          // [n_rows * 16] float4
    const int* __restrict__ index,          // [n_rows] int32
    float* __restrict__ out,                // [num_seg * 64]
    int n_rows)
{
    int tid  = blockIdx.x * blockDim.x + threadIdx.x;
    int row  = tid >> 4;
    int lane = tid & 15;
    if (row >= n_rows) return;

    int seg = index[row];
    float4 v = x4[(size_t)row * 16 + lane];

    float* dst = out + (size_t)seg * DIM + lane * 4;
    asm volatile("red.global.add.v4.f32 [%0], {%1, %2, %3, %4};"
                 :: "l"(dst), "f"(v.x), "f"(v.y), "f"(v.z), "f"(v.w)
                 : "memory");

    if (lane == 0)
        atomicAdd(&g_counts[seg], 1.0f);   // -> RED.ADD.F32 (result unused)
}

// ---------------------------------------------------------------------------
// Kernel 3: divide sums by max(count, 1). One thread per output element.
// ---------------------------------------------------------------------------
__global__ void finalize_kernel(float* __restrict__ out, int n_out) {
    int i = blockIdx.x * blockDim.x + threadIdx.x;
    if (i >= n_out) return;
    int seg = i >> 6;                       // i / 64
    float c = g_counts[seg];
    out[i] = out[i] * (1.0f / fmaxf(c, 1.0f));
}

// ---------------------------------------------------------------------------
// Launch. Inputs per metadata: [0]=x float32 [N,64], [1]=index int32 [N],
// [2]=num_segments (scalar). Output: float32 [num_seg, 64].
// ---------------------------------------------------------------------------
extern "C" void kernel_launch(void* const* d_in, const int* in_sizes, int n_in,
                              void* d_out, int out_size)
{
    const float4* x4  = (const float4*)d_in[0];
    const int*    idx = (const int*)d_in[1];
    float*        out = (float*)d_out;

    int n_rows  = in_sizes[0] / DIM;
    int num_seg = out_size / DIM;
    if (num_seg > MAX_SEG) num_seg = MAX_SEG;

    // 1) zero sums + counts
    {
        int n_out4 = out_size / 4;
        zero_kernel<<<1024, 256>>>((float4*)d_out, n_out4, num_seg);
    }

    // 2) scatter-add (16 threads per row)
    {
        long long total_threads = (long long)n_rows * 16;
        int threads = 256;
        long long blocks = (total_threads + threads - 1) / threads;
        scatter_kernel<<<(unsigned)blocks, threads>>>(x4, idx, out, n_rows);
    }

    // 3) finalize: divide by counts
    {
        int threads = 256;
        int blocks = (out_size + threads - 1) / threads;
        finalize_kernel<<<blocks, threads>>>(out, out_size);
    }
}